// round 7
// baseline (speedup 1.0000x reference)
#include <cuda_runtime.h>

#define BATCH 2048
#define T 128
#define NS 16
#define MS 8
#define CS 4
#define DT 0.01f

// Batch-independent gain sequences (small, L2-resident).
__device__ float g_K[T * MS * NS];              // K[t][q][i] = K[i][q]
__device__ float g_Pf[(T - 1) * NS * NS];       // P_f[t], t = 0..T-2
__device__ float g_Xs[(T - 1) * NS * NS];       // X[t] = G[t]^T, t = 0..T-2

__device__ __forceinline__ float4 ld4(const float* p) { return *reinterpret_cast<const float4*>(p); }
__device__ __forceinline__ void st4(float* p, float4 v) { *reinterpret_cast<float4*>(p) = v; }
__device__ __forceinline__ float rcpa(float x) { float y; asm("rcp.approx.f32 %0, %1;" : "=f"(y) : "f"(x)); return y; }
__device__ __forceinline__ float shfl(float v, int s) { return __shfl_sync(0xffffffffu, v, s); }
__device__ __forceinline__ float shflx(float v, int m) { return __shfl_xor_sync(0xffffffffu, v, m); }
__device__ __forceinline__ float shfl16(float v, int s) { return __shfl_sync(0xffffffffu, v, s, 16); }

// ============================================================================
// Kernel A: batch-independent Riccati recursion (ONE warp, serial over T).
// ============================================================================
__global__ __launch_bounds__(32) void kf_gains(
    const float* __restrict__ P0, const float* __restrict__ A,
    const float* __restrict__ H, const float* __restrict__ Q,
    const float* __restrict__ R)
{
    __shared__ float Fb[16 * 20], Ftb[16 * 20], Qb[16 * 20];
    __shared__ float Hb[8 * 20], Ht[16 * 8], Rb[64];
    __shared__ float P[16 * 20], PHt[16 * 8], X2[8 * 20];

    const int lane = threadIdx.x;
    for (int idx = lane; idx < 256; idx += 32) {
        int i = idx >> 4, k = idx & 15;
        float a = A[idx];
        float f = (i == k ? 1.0f : 0.0f) + DT * a;
        Fb[i * 20 + k] = f; Ftb[k * 20 + i] = f;
        Qb[i * 20 + k] = Q[idx];
        P[i * 20 + k] = P0[idx];
    }
    for (int idx = lane; idx < 128; idx += 32) {
        int q = idx >> 4, k = idx & 15;
        float h = H[idx];
        Hb[q * 20 + k] = h; Ht[k * 8 + q] = h;
    }
    for (int idx = lane; idx < 64; idx += 32) Rb[idx] = R[idx];
    __syncwarp();

    const int row = lane >> 1, h = lane & 1, j0 = h * 8;
    const int rr = row & 7;

    float frow[16];
    #pragma unroll
    for (int k = 0; k < 16; ++k) frow[k] = Fb[row * 20 + k];

    float a[8], w[8];

    for (int t = 0; t < T; ++t) {
        // Phase 1: W = F * P
        #pragma unroll
        for (int j = 0; j < 8; ++j) w[j] = 0.0f;
        #pragma unroll
        for (int k = 0; k < 16; ++k) {
            float fv = frow[k];
            float4 p0 = ld4(&P[k * 20 + j0]);
            float4 p1 = ld4(&P[k * 20 + j0 + 4]);
            w[0] = fmaf(fv, p0.x, w[0]); w[1] = fmaf(fv, p0.y, w[1]);
            w[2] = fmaf(fv, p0.z, w[2]); w[3] = fmaf(fv, p0.w, w[3]);
            w[4] = fmaf(fv, p1.x, w[4]); w[5] = fmaf(fv, p1.y, w[5]);
            w[6] = fmaf(fv, p1.z, w[6]); w[7] = fmaf(fv, p1.w, w[7]);
        }

        // Phase 2: PP = W * F^T + Q  (kept in regs a[])
        {
            float wk[16];
            #pragma unroll
            for (int j = 0; j < 8; ++j) {
                wk[j0 + j] = w[j];
                wk[(j0 ^ 8) + j] = shflx(w[j], 1);
            }
            float4 q0 = ld4(&Qb[row * 20 + j0]);
            float4 q1 = ld4(&Qb[row * 20 + j0 + 4]);
            a[0] = q0.x; a[1] = q0.y; a[2] = q0.z; a[3] = q0.w;
            a[4] = q1.x; a[5] = q1.y; a[6] = q1.z; a[7] = q1.w;
            #pragma unroll
            for (int k = 0; k < 16; ++k) {
                float wv = wk[k];
                float4 f0 = ld4(&Ftb[k * 20 + j0]);
                float4 f1 = ld4(&Ftb[k * 20 + j0 + 4]);
                a[0] = fmaf(wv, f0.x, a[0]); a[1] = fmaf(wv, f0.y, a[1]);
                a[2] = fmaf(wv, f0.z, a[2]); a[3] = fmaf(wv, f0.w, a[3]);
                a[4] = fmaf(wv, f1.x, a[4]); a[5] = fmaf(wv, f1.y, a[5]);
                a[6] = fmaf(wv, f1.z, a[6]); a[7] = fmaf(wv, f1.w, a[7]);
            }
        }

        // Phase 3: PHt[i][q] = sum_k PP[i][k] * H[q][k]
        {
            float pk[16];
            #pragma unroll
            for (int j = 0; j < 8; ++j) {
                pk[j0 + j] = a[j];
                pk[(j0 ^ 8) + j] = shflx(a[j], 1);
            }
            const int qh = h * 4;
            float4 acc = make_float4(0.f, 0.f, 0.f, 0.f);
            #pragma unroll
            for (int k = 0; k < 16; ++k) {
                float p = pk[k];
                float4 hv = ld4(&Ht[k * 8 + qh]);
                acc.x = fmaf(p, hv.x, acc.x); acc.y = fmaf(p, hv.y, acc.y);
                acc.z = fmaf(p, hv.z, acc.z); acc.w = fmaf(p, hv.w, acc.w);
            }
            st4(&PHt[row * 8 + qh], acc);
        }
        __syncwarp();

        // Phase 4: S rows + RHS rows into registers
        float s4[4], rhs[8];
        {
            const int ch = h * 4;
            s4[0] = Rb[rr * 8 + ch];     s4[1] = Rb[rr * 8 + ch + 1];
            s4[2] = Rb[rr * 8 + ch + 2]; s4[3] = Rb[rr * 8 + ch + 3];
            #pragma unroll
            for (int k = 0; k < 16; ++k) {
                float hv = Hb[rr * 20 + k];
                float4 ph = ld4(&PHt[k * 8 + ch]);
                s4[0] = fmaf(hv, ph.x, s4[0]); s4[1] = fmaf(hv, ph.y, s4[1]);
                s4[2] = fmaf(hv, ph.z, s4[2]); s4[3] = fmaf(hv, ph.w, s4[3]);
            }
            #pragma unroll
            for (int j = 0; j < 8; ++j)
                rhs[j] = PHt[(h * 8 + j) * 8 + rr];
        }

        // Phase 5: GJ solve S * X2 = PHt^T (8x8); X2 = K^T
        {
            #pragma unroll
            for (int p = 0; p < 8; ++p) {
                const int hp = (p >= 4) ? 1 : 0;
                float cand = s4[p & 3];
                float f_num = shfl(cand, (rr << 1) | hp);
                float diag  = shfl(cand, (p << 1) | hp);
                const int src = (p << 1) | h;
                float ps0 = shfl(s4[0], src), ps1 = shfl(s4[1], src);
                float ps2 = shfl(s4[2], src), ps3 = shfl(s4[3], src);
                float pr[8];
                #pragma unroll
                for (int j = 0; j < 8; ++j) pr[j] = shfl(rhs[j], src);
                float f = (rr == p) ? 0.0f : f_num * rcpa(diag);
                s4[0] = fmaf(-f, ps0, s4[0]); s4[1] = fmaf(-f, ps1, s4[1]);
                s4[2] = fmaf(-f, ps2, s4[2]); s4[3] = fmaf(-f, ps3, s4[3]);
                #pragma unroll
                for (int j = 0; j < 8; ++j) rhs[j] = fmaf(-f, pr[j], rhs[j]);
            }
            float s01 = (rr & 1) ? s4[1] : s4[0];
            float s23 = (rr & 1) ? s4[3] : s4[2];
            float cand_r = (rr & 2) ? s23 : s01;
            float diag_r = shfl(cand_r, (rr << 1) | ((rr >= 4) ? 1 : 0));
            float invd = rcpa(diag_r);
            if (lane < 16) {
                float4 x0 = make_float4(rhs[0] * invd, rhs[1] * invd, rhs[2] * invd, rhs[3] * invd);
                float4 x1 = make_float4(rhs[4] * invd, rhs[5] * invd, rhs[6] * invd, rhs[7] * invd);
                st4(&X2[rr * 20 + h * 8], x0);
                st4(&X2[rr * 20 + h * 8 + 4], x1);
                st4(&g_K[t * 128 + rr * 16 + h * 8], x0);
                st4(&g_K[t * 128 + rr * 16 + h * 8 + 4], x1);
            }
        }
        __syncwarp();

        // Phase 8: P_f = PP - K * (H*PP);  (H*PP)[q][j] = PHt[j][q] (PP symmetric).
        // Vectorized: PHt rows are contiguous 8-float runs.
        {
            float kq[8];
            #pragma unroll
            for (int q = 0; q < 8; ++q) kq[q] = X2[q * 20 + row];   // K[row][q]
            float n[8];
            #pragma unroll
            for (int j = 0; j < 8; ++j) {
                float4 p0 = ld4(&PHt[(j0 + j) * 8]);
                float4 p1 = ld4(&PHt[(j0 + j) * 8 + 4]);
                float v = a[j];
                v = fmaf(-kq[0], p0.x, v); v = fmaf(-kq[1], p0.y, v);
                v = fmaf(-kq[2], p0.z, v); v = fmaf(-kq[3], p0.w, v);
                v = fmaf(-kq[4], p1.x, v); v = fmaf(-kq[5], p1.y, v);
                v = fmaf(-kq[6], p1.z, v); v = fmaf(-kq[7], p1.w, v);
                n[j] = v;
            }
            float4 v0 = make_float4(n[0], n[1], n[2], n[3]);
            float4 v1 = make_float4(n[4], n[5], n[6], n[7]);
            st4(&P[row * 20 + j0], v0);
            st4(&P[row * 20 + j0 + 4], v1);
            if (t < T - 1) {
                st4(&g_Pf[t * 256 + row * 16 + j0], v0);
                st4(&g_Pf[t * 256 + row * 16 + j0 + 4], v1);
            }
        }
        __syncwarp();
    }
}

// ============================================================================
// Kernel B: smoother gains, T-1 parallel warps. X[t] = P_p[t+1]^-1 * F * P_f[t].
// ============================================================================
__global__ __launch_bounds__(32) void kf_smoother_gains(
    const float* __restrict__ A, const float* __restrict__ Q)
{
    __shared__ float Fb[16 * 20], Ftb[16 * 20], Qb[16 * 20], Pf[16 * 20];
    const int t = blockIdx.x;
    const int lane = threadIdx.x;

    for (int idx = lane; idx < 256; idx += 32) {
        int i = idx >> 4, k = idx & 15;
        float av = A[idx];
        float f = (i == k ? 1.0f : 0.0f) + DT * av;
        Fb[i * 20 + k] = f; Ftb[k * 20 + i] = f;
        Qb[i * 20 + k] = Q[idx];
        Pf[i * 20 + k] = g_Pf[t * 256 + idx];
    }
    __syncwarp();

    const int row = lane >> 1, h = lane & 1, j0 = h * 8;
    float frow[16];
    #pragma unroll
    for (int k = 0; k < 16; ++k) frow[k] = Fb[row * 20 + k];

    float a[8], w[8];
    #pragma unroll
    for (int j = 0; j < 8; ++j) w[j] = 0.0f;
    #pragma unroll
    for (int k = 0; k < 16; ++k) {
        float fv = frow[k];
        float4 p0 = ld4(&Pf[k * 20 + j0]);
        float4 p1 = ld4(&Pf[k * 20 + j0 + 4]);
        w[0] = fmaf(fv, p0.x, w[0]); w[1] = fmaf(fv, p0.y, w[1]);
        w[2] = fmaf(fv, p0.z, w[2]); w[3] = fmaf(fv, p0.w, w[3]);
        w[4] = fmaf(fv, p1.x, w[4]); w[5] = fmaf(fv, p1.y, w[5]);
        w[6] = fmaf(fv, p1.z, w[6]); w[7] = fmaf(fv, p1.w, w[7]);
    }
    {
        float wk[16];
        #pragma unroll
        for (int j = 0; j < 8; ++j) {
            wk[j0 + j] = w[j];
            wk[(j0 ^ 8) + j] = shflx(w[j], 1);
        }
        float4 q0 = ld4(&Qb[row * 20 + j0]);
        float4 q1 = ld4(&Qb[row * 20 + j0 + 4]);
        a[0] = q0.x; a[1] = q0.y; a[2] = q0.z; a[3] = q0.w;
        a[4] = q1.x; a[5] = q1.y; a[6] = q1.z; a[7] = q1.w;
        #pragma unroll
        for (int k = 0; k < 16; ++k) {
            float wv = wk[k];
            float4 f0 = ld4(&Ftb[k * 20 + j0]);
            float4 f1 = ld4(&Ftb[k * 20 + j0 + 4]);
            a[0] = fmaf(wv, f0.x, a[0]); a[1] = fmaf(wv, f0.y, a[1]);
            a[2] = fmaf(wv, f0.z, a[2]); a[3] = fmaf(wv, f0.w, a[3]);
            a[4] = fmaf(wv, f1.x, a[4]); a[5] = fmaf(wv, f1.y, a[5]);
            a[6] = fmaf(wv, f1.z, a[6]); a[7] = fmaf(wv, f1.w, a[7]);
        }
    }
    #pragma unroll
    for (int p = 0; p < 16; ++p) {
        const int hp = (p >= 8) ? 1 : 0;
        float cand = a[p & 7];
        float f_num = shfl(cand, (row << 1) | hp);
        float diag  = shfl(cand, (p << 1) | hp);
        const int src = (p << 1) | h;
        float pa[8], pw[8];
        #pragma unroll
        for (int j = 0; j < 8; ++j) { pa[j] = shfl(a[j], src); pw[j] = shfl(w[j], src); }
        float f = (row == p) ? 0.0f : f_num * rcpa(diag);
        #pragma unroll
        for (int j = 0; j < 8; ++j) {
            a[j] = fmaf(-f, pa[j], a[j]);
            w[j] = fmaf(-f, pw[j], w[j]);
        }
    }
    const int ri = row & 7;
    float s01 = (ri & 1) ? a[1] : a[0];
    float s23 = (ri & 1) ? a[3] : a[2];
    float s45 = (ri & 1) ? a[5] : a[4];
    float s67 = (ri & 1) ? a[7] : a[6];
    float t0 = (ri & 2) ? s23 : s01;
    float t1 = (ri & 2) ? s67 : s45;
    float cand_r = (ri & 4) ? t1 : t0;
    float diag_r = shfl(cand_r, (row << 1) | ((row >= 8) ? 1 : 0));
    float invd = rcpa(diag_r);
    st4(&g_Xs[t * 256 + row * 16 + j0],
        make_float4(w[0] * invd, w[1] * invd, w[2] * invd, w[3] * invd));
    st4(&g_Xs[t * 256 + row * 16 + j0 + 4],
        make_float4(w[4] * invd, w[5] * invd, w[6] * invd, w[7] * invd));
}

// ============================================================================
// Kernel C: forward state filter, ILP x2 (4 batches/warp: 2 lane-wise x 2 regs).
// ============================================================================
__global__ __launch_bounds__(64) void kf_states(
    const float* __restrict__ state0, const float* __restrict__ controls,
    const float* __restrict__ obs, const float* __restrict__ A,
    const float* __restrict__ Bc, const float* __restrict__ H,
    float* __restrict__ out)
{
    const int L = threadIdx.x & 31;
    const int wid = blockIdx.x * 2 + (threadIdx.x >> 5);
    const int i = L & 15;
    const int b0 = wid * 4 + (L >> 4);
    const int b1 = b0 + 2;

    float arow[16], hrow[16], brow[4];
    #pragma unroll
    for (int k = 0; k < 16; ++k) arow[k] = A[i * 16 + k];
    #pragma unroll
    for (int k = 0; k < 16; ++k) hrow[k] = H[(i & 7) * 16 + k];
    #pragma unroll
    for (int c = 0; c < 4; ++c) brow[c] = Bc[i * 4 + c];

    float s0 = state0[b0 * 16 + i];
    float s1 = state0[b1 * 16 + i];

    // prefetch t=0 data
    float kq[8], u0[4], u1[4], y0, y1;
    #pragma unroll
    for (int q = 0; q < 8; ++q) kq[q] = g_K[q * 16 + i];
    #pragma unroll
    for (int c = 0; c < 4; ++c) { u0[c] = controls[(size_t)b0 * T * 4 + c]; u1[c] = controls[(size_t)b1 * T * 4 + c]; }
    y0 = obs[(size_t)b0 * T * 8 + (i & 7)];
    y1 = obs[(size_t)b1 * T * 8 + (i & 7)];

    #pragma unroll 1
    for (int t = 0; t < T; ++t) {
        float kqn[8], u0n[4], u1n[4], y0n = 0.f, y1n = 0.f;
        if (t + 1 < T) {
            #pragma unroll
            for (int q = 0; q < 8; ++q) kqn[q] = g_K[(t + 1) * 128 + q * 16 + i];
            #pragma unroll
            for (int c = 0; c < 4; ++c) {
                u0n[c] = controls[((size_t)b0 * T + t + 1) * 4 + c];
                u1n[c] = controls[((size_t)b1 * T + t + 1) * 4 + c];
            }
            y0n = obs[((size_t)b0 * T + t + 1) * 8 + (i & 7)];
            y1n = obs[((size_t)b1 * T + t + 1) * 8 + (i & 7)];
        } else {
            #pragma unroll
            for (int q = 0; q < 8; ++q) kqn[q] = 0.f;
            #pragma unroll
            for (int c = 0; c < 4; ++c) { u0n[c] = 0.f; u1n[c] = 0.f; }
        }

        // chain 0 + chain 1 interleaved
        float a00 = 0.f, a01 = 0.f, a10 = 0.f, a11 = 0.f;
        #pragma unroll
        for (int k = 0; k < 8; ++k) {
            a00 = fmaf(arow[k], shfl16(s0, k), a00);
            a10 = fmaf(arow[k], shfl16(s1, k), a10);
            a01 = fmaf(arow[k + 8], shfl16(s0, k + 8), a01);
            a11 = fmaf(arow[k + 8], shfl16(s1, k + 8), a11);
        }
        #pragma unroll
        for (int c = 0; c < 4; ++c) {
            a00 = fmaf(brow[c], u0[c], a00);
            a10 = fmaf(brow[c], u1[c], a10);
        }
        float sp0 = s0 + DT * (a00 + a01);
        float sp1 = s1 + DT * (a10 + a11);

        float h00 = 0.f, h01 = 0.f, h10 = 0.f, h11 = 0.f;
        #pragma unroll
        for (int k = 0; k < 8; ++k) {
            h00 = fmaf(hrow[k], shfl16(sp0, k), h00);
            h10 = fmaf(hrow[k], shfl16(sp1, k), h10);
            h01 = fmaf(hrow[k + 8], shfl16(sp0, k + 8), h01);
            h11 = fmaf(hrow[k + 8], shfl16(sp1, k + 8), h11);
        }
        float iv0 = y0 - (h00 + h01);
        float iv1 = y1 - (h10 + h11);

        float acc0 = sp0, acc1 = sp1;
        #pragma unroll
        for (int q = 0; q < 8; ++q) {
            acc0 = fmaf(kq[q], shfl16(iv0, q), acc0);
            acc1 = fmaf(kq[q], shfl16(iv1, q), acc1);
        }
        s0 = acc0; s1 = acc1;
        out[((size_t)b0 * T + t) * NS + i] = s0;
        out[((size_t)b1 * T + t) * NS + i] = s1;

        #pragma unroll
        for (int q = 0; q < 8; ++q) kq[q] = kqn[q];
        #pragma unroll
        for (int c = 0; c < 4; ++c) { u0[c] = u0n[c]; u1[c] = u1n[c]; }
        y0 = y0n; y1 = y1n;
    }
}

// ============================================================================
// Kernel D: backward smoother, ILP x2. s_p recomputed; Xs shared across chains.
// ============================================================================
__global__ __launch_bounds__(64) void kf_backward(
    const float* __restrict__ controls, const float* __restrict__ A,
    const float* __restrict__ Bc, float* __restrict__ out)
{
    const int L = threadIdx.x & 31;
    const int wid = blockIdx.x * 2 + (threadIdx.x >> 5);
    const int i = L & 15;
    const int b0 = wid * 4 + (L >> 4);
    const int b1 = b0 + 2;

    float arow[16], brow[4];
    #pragma unroll
    for (int k = 0; k < 16; ++k) arow[k] = A[i * 16 + k];
    #pragma unroll
    for (int c = 0; c < 4; ++c) brow[c] = Bc[i * 4 + c];

    float ss0 = out[((size_t)b0 * T + (T - 1)) * NS + i];
    float ss1 = out[((size_t)b1 * T + (T - 1)) * NS + i];
    float sf0 = out[((size_t)b0 * T + (T - 2)) * NS + i];
    float sf1 = out[((size_t)b1 * T + (T - 2)) * NS + i];

    float xc[16];
    #pragma unroll
    for (int j = 0; j < 16; ++j) xc[j] = g_Xs[(T - 2) * 256 + j * 16 + i];

    #pragma unroll 1
    for (int t = T - 2; t >= 0; --t) {
        float xn[16], sfn0 = 0.f, sfn1 = 0.f;
        if (t > 0) {
            #pragma unroll
            for (int j = 0; j < 16; ++j) xn[j] = g_Xs[(t - 1) * 256 + j * 16 + i];
            sfn0 = out[((size_t)b0 * T + t - 1) * NS + i];
            sfn1 = out[((size_t)b1 * T + t - 1) * NS + i];
        }
        float u0c = (i < 4) ? controls[((size_t)b0 * T + t + 1) * 4 + i] : 0.f;
        float u1c = (i < 4) ? controls[((size_t)b1 * T + t + 1) * 4 + i] : 0.f;

        // s_p[t+1] = sf + DT*(A sf + Bc u[t+1]), both chains
        float a00 = 0.f, a01 = 0.f, a10 = 0.f, a11 = 0.f;
        #pragma unroll
        for (int k = 0; k < 8; ++k) {
            a00 = fmaf(arow[k], shfl16(sf0, k), a00);
            a10 = fmaf(arow[k], shfl16(sf1, k), a10);
            a01 = fmaf(arow[k + 8], shfl16(sf0, k + 8), a01);
            a11 = fmaf(arow[k + 8], shfl16(sf1, k + 8), a11);
        }
        #pragma unroll
        for (int c = 0; c < 4; ++c) {
            a00 = fmaf(brow[c], shfl16(u0c, c), a00);
            a10 = fmaf(brow[c], shfl16(u1c, c), a10);
        }
        float sp0 = sf0 + DT * (a00 + a01);
        float sp1 = sf1 + DT * (a10 + a11);

        float d0 = ss0 - sp0;
        float d1 = ss1 - sp1;
        float m00 = 0.f, m01 = 0.f, m10 = 0.f, m11 = 0.f;
        #pragma unroll
        for (int j = 0; j < 8; ++j) {
            m00 = fmaf(shfl16(d0, j), xc[j], m00);
            m10 = fmaf(shfl16(d1, j), xc[j], m10);
            m01 = fmaf(shfl16(d0, j + 8), xc[j + 8], m01);
            m11 = fmaf(shfl16(d1, j + 8), xc[j + 8], m11);
        }
        ss0 = sf0 + m00 + m01;
        ss1 = sf1 + m10 + m11;
        out[((size_t)b0 * T + t) * NS + i] = ss0;
        out[((size_t)b1 * T + t) * NS + i] = ss1;

        if (t > 0) {
            #pragma unroll
            for (int j = 0; j < 16; ++j) xc[j] = xn[j];
            sf0 = sfn0; sf1 = sfn1;
        }
    }
}

extern "C" void kernel_launch(void* const* d_in, const int* in_sizes, int n_in,
                              void* d_out, int out_size) {
    (void)in_sizes; (void)n_in; (void)out_size;
    const float* state0   = (const float*)d_in[0];
    const float* P0       = (const float*)d_in[1];
    const float* controls = (const float*)d_in[2];
    const float* obs      = (const float*)d_in[3];
    const float* A        = (const float*)d_in[4];
    const float* Bc       = (const float*)d_in[5];
    const float* H        = (const float*)d_in[6];
    const float* Q        = (const float*)d_in[7];
    const float* R        = (const float*)d_in[8];
    float* out = (float*)d_out;

    kf_gains<<<1, 32>>>(P0, A, H, Q, R);
    kf_smoother_gains<<<T - 1, 32>>>(A, Q);
    kf_states<<<BATCH / 8, 64>>>(state0, controls, obs, A, Bc, H, out);
    kf_backward<<<BATCH / 8, 64>>>(controls, A, Bc, out);
}

// round 8
// speedup vs baseline: 1.1146x; 1.1146x over previous
#include <cuda_runtime.h>

#define BATCH 2048
#define T 128
#define NS 16
#define MS 8
#define CS 4
#define DT 0.01f

// Batch-independent gain sequences (small, L2-resident).
__device__ float g_K[T * MS * NS];              // K[t][q][i] = K[i][q]
__device__ float g_Pf[(T - 1) * NS * NS];       // P_f[t], t = 0..T-2
__device__ float g_Xs[(T - 1) * NS * NS];       // X[t] = G[t]^T, t = 0..T-2
__device__ float g_sp[(size_t)BATCH * T * NS];  // predicted states (t>=1 used)
__device__ int   g_flag[T];                     // per-step publish flags

__device__ __forceinline__ float4 ld4(const float* p) { return *reinterpret_cast<const float4*>(p); }
__device__ __forceinline__ void st4(float* p, float4 v) { *reinterpret_cast<float4*>(p) = v; }
__device__ __forceinline__ float rcpa(float x) { float y; asm("rcp.approx.f32 %0, %1;" : "=f"(y) : "f"(x)); return y; }
__device__ __forceinline__ float shfl(float v, int s) { return __shfl_sync(0xffffffffu, v, s); }
__device__ __forceinline__ float shflx(float v, int m) { return __shfl_xor_sync(0xffffffffu, v, m); }
__device__ __forceinline__ float shfl16(float v, int s) { return __shfl_sync(0xffffffffu, v, s, 16); }

__device__ __forceinline__ void flag_rel(int t) {
    asm volatile("st.release.gpu.b32 [%0], %1;" :: "l"(g_flag + t), "r"(1) : "memory");
}
__device__ __forceinline__ int flag_acq(int t) {
    int v;
    asm volatile("ld.acquire.gpu.b32 %0, [%1];" : "=r"(v) : "l"(g_flag + t) : "memory");
    return v;
}
__device__ __forceinline__ void wait_flag(int t) {
    while (!flag_acq(t)) __nanosleep(64);
}

__global__ void kf_reset() {
    int i = threadIdx.x;
    if (i < T) g_flag[i] = 0;
}

// ============================================================================
// Fused kernel: block 0 = Riccati producer; blocks 1..32 = smoother gains;
// blocks 33..288 = forward state filter (consumers of K[t] via flags).
// ============================================================================
__global__ __launch_bounds__(128) void kf_fused(
    const float* __restrict__ state0, const float* __restrict__ P0,
    const float* __restrict__ controls, const float* __restrict__ obs,
    const float* __restrict__ A, const float* __restrict__ Bc,
    const float* __restrict__ H, const float* __restrict__ Q,
    const float* __restrict__ R, float* __restrict__ out)
{
    __shared__ float Fb[16 * 20], Ftb[16 * 20], Qb[16 * 20];       // gains + smoother
    __shared__ float Hb[8 * 20], Ht[16 * 8], Rb[64];                // gains only
    __shared__ float P[16 * 20], PHt[16 * 8], X2[8 * 20];           // gains only
    __shared__ float Pfw[4][16 * 20];                               // smoother per-warp

    const int bid = blockIdx.x;
    const int tid = threadIdx.x;
    const int wrp = tid >> 5;
    const int lane = tid & 31;

    // ------------------------------------------------------------------
    // Role 1: Riccati recursion (block 0, warp 0)
    // ------------------------------------------------------------------
    if (bid == 0) {
        if (wrp != 0) return;

        for (int idx = lane; idx < 256; idx += 32) {
            int i = idx >> 4, k = idx & 15;
            float a = A[idx];
            float f = (i == k ? 1.0f : 0.0f) + DT * a;
            Fb[i * 20 + k] = f; Ftb[k * 20 + i] = f;
            Qb[i * 20 + k] = Q[idx];
            P[i * 20 + k] = P0[idx];
        }
        for (int idx = lane; idx < 128; idx += 32) {
            int q = idx >> 4, k = idx & 15;
            float h = H[idx];
            Hb[q * 20 + k] = h; Ht[k * 8 + q] = h;
        }
        for (int idx = lane; idx < 64; idx += 32) Rb[idx] = R[idx];
        __syncwarp();

        const int row = lane >> 1, h = lane & 1, j0 = h * 8;
        const int rr = row & 7;

        float frow[16];
        #pragma unroll
        for (int k = 0; k < 16; ++k) frow[k] = Fb[row * 20 + k];

        float a[8], w[8];

        for (int t = 0; t < T; ++t) {
            // Phase 1: W = F * P
            #pragma unroll
            for (int j = 0; j < 8; ++j) w[j] = 0.0f;
            #pragma unroll
            for (int k = 0; k < 16; ++k) {
                float fv = frow[k];
                float4 p0 = ld4(&P[k * 20 + j0]);
                float4 p1 = ld4(&P[k * 20 + j0 + 4]);
                w[0] = fmaf(fv, p0.x, w[0]); w[1] = fmaf(fv, p0.y, w[1]);
                w[2] = fmaf(fv, p0.z, w[2]); w[3] = fmaf(fv, p0.w, w[3]);
                w[4] = fmaf(fv, p1.x, w[4]); w[5] = fmaf(fv, p1.y, w[5]);
                w[6] = fmaf(fv, p1.z, w[6]); w[7] = fmaf(fv, p1.w, w[7]);
            }

            // Phase 2: PP = W * F^T + Q (regs a[])
            {
                float wk[16];
                #pragma unroll
                for (int j = 0; j < 8; ++j) {
                    wk[j0 + j] = w[j];
                    wk[(j0 ^ 8) + j] = shflx(w[j], 1);
                }
                float4 q0 = ld4(&Qb[row * 20 + j0]);
                float4 q1 = ld4(&Qb[row * 20 + j0 + 4]);
                a[0] = q0.x; a[1] = q0.y; a[2] = q0.z; a[3] = q0.w;
                a[4] = q1.x; a[5] = q1.y; a[6] = q1.z; a[7] = q1.w;
                #pragma unroll
                for (int k = 0; k < 16; ++k) {
                    float wv = wk[k];
                    float4 f0 = ld4(&Ftb[k * 20 + j0]);
                    float4 f1 = ld4(&Ftb[k * 20 + j0 + 4]);
                    a[0] = fmaf(wv, f0.x, a[0]); a[1] = fmaf(wv, f0.y, a[1]);
                    a[2] = fmaf(wv, f0.z, a[2]); a[3] = fmaf(wv, f0.w, a[3]);
                    a[4] = fmaf(wv, f1.x, a[4]); a[5] = fmaf(wv, f1.y, a[5]);
                    a[6] = fmaf(wv, f1.z, a[6]); a[7] = fmaf(wv, f1.w, a[7]);
                }
            }

            // Phase 3: PHt[i][q] = sum_k PP[i][k] * H[q][k]
            {
                float pk[16];
                #pragma unroll
                for (int j = 0; j < 8; ++j) {
                    pk[j0 + j] = a[j];
                    pk[(j0 ^ 8) + j] = shflx(a[j], 1);
                }
                const int qh = h * 4;
                float4 acc = make_float4(0.f, 0.f, 0.f, 0.f);
                #pragma unroll
                for (int k = 0; k < 16; ++k) {
                    float p = pk[k];
                    float4 hv = ld4(&Ht[k * 8 + qh]);
                    acc.x = fmaf(p, hv.x, acc.x); acc.y = fmaf(p, hv.y, acc.y);
                    acc.z = fmaf(p, hv.z, acc.z); acc.w = fmaf(p, hv.w, acc.w);
                }
                st4(&PHt[row * 8 + qh], acc);
            }
            __syncwarp();

            // Phase 4: S rows + RHS rows into registers
            float s4[4], rhs[8];
            {
                const int ch = h * 4;
                s4[0] = Rb[rr * 8 + ch];     s4[1] = Rb[rr * 8 + ch + 1];
                s4[2] = Rb[rr * 8 + ch + 2]; s4[3] = Rb[rr * 8 + ch + 3];
                #pragma unroll
                for (int k = 0; k < 16; ++k) {
                    float hv = Hb[rr * 20 + k];
                    float4 ph = ld4(&PHt[k * 8 + ch]);
                    s4[0] = fmaf(hv, ph.x, s4[0]); s4[1] = fmaf(hv, ph.y, s4[1]);
                    s4[2] = fmaf(hv, ph.z, s4[2]); s4[3] = fmaf(hv, ph.w, s4[3]);
                }
                #pragma unroll
                for (int j = 0; j < 8; ++j)
                    rhs[j] = PHt[(h * 8 + j) * 8 + rr];
            }

            // Phase 5: GJ solve S * X2 = PHt^T (8x8); X2 = K^T
            {
                #pragma unroll
                for (int p = 0; p < 8; ++p) {
                    const int hp = (p >= 4) ? 1 : 0;
                    float cand = s4[p & 3];
                    float f_num = shfl(cand, (rr << 1) | hp);
                    float diag  = shfl(cand, (p << 1) | hp);
                    const int src = (p << 1) | h;
                    float ps0 = shfl(s4[0], src), ps1 = shfl(s4[1], src);
                    float ps2 = shfl(s4[2], src), ps3 = shfl(s4[3], src);
                    float pr[8];
                    #pragma unroll
                    for (int j = 0; j < 8; ++j) pr[j] = shfl(rhs[j], src);
                    float f = (rr == p) ? 0.0f : f_num * rcpa(diag);
                    s4[0] = fmaf(-f, ps0, s4[0]); s4[1] = fmaf(-f, ps1, s4[1]);
                    s4[2] = fmaf(-f, ps2, s4[2]); s4[3] = fmaf(-f, ps3, s4[3]);
                    #pragma unroll
                    for (int j = 0; j < 8; ++j) rhs[j] = fmaf(-f, pr[j], rhs[j]);
                }
                float s01 = (rr & 1) ? s4[1] : s4[0];
                float s23 = (rr & 1) ? s4[3] : s4[2];
                float cand_r = (rr & 2) ? s23 : s01;
                float diag_r = shfl(cand_r, (rr << 1) | ((rr >= 4) ? 1 : 0));
                float invd = rcpa(diag_r);
                if (lane < 16) {
                    float4 x0 = make_float4(rhs[0] * invd, rhs[1] * invd, rhs[2] * invd, rhs[3] * invd);
                    float4 x1 = make_float4(rhs[4] * invd, rhs[5] * invd, rhs[6] * invd, rhs[7] * invd);
                    st4(&X2[rr * 20 + h * 8], x0);
                    st4(&X2[rr * 20 + h * 8 + 4], x1);
                    st4(&g_K[t * 128 + rr * 16 + h * 8], x0);
                    st4(&g_K[t * 128 + rr * 16 + h * 8 + 4], x1);
                }
            }
            __syncwarp();

            // Phase 8: P_f = PP - K * (H*PP);  (H*PP)[q][j] = PHt[j][q].
            {
                float kq[8];
                #pragma unroll
                for (int q = 0; q < 8; ++q) kq[q] = X2[q * 20 + row];
                float n[8];
                #pragma unroll
                for (int j = 0; j < 8; ++j) {
                    float4 p0 = ld4(&PHt[(j0 + j) * 8]);
                    float4 p1 = ld4(&PHt[(j0 + j) * 8 + 4]);
                    float v = a[j];
                    v = fmaf(-kq[0], p0.x, v); v = fmaf(-kq[1], p0.y, v);
                    v = fmaf(-kq[2], p0.z, v); v = fmaf(-kq[3], p0.w, v);
                    v = fmaf(-kq[4], p1.x, v); v = fmaf(-kq[5], p1.y, v);
                    v = fmaf(-kq[6], p1.z, v); v = fmaf(-kq[7], p1.w, v);
                    n[j] = v;
                }
                float4 v0 = make_float4(n[0], n[1], n[2], n[3]);
                float4 v1 = make_float4(n[4], n[5], n[6], n[7]);
                st4(&P[row * 20 + j0], v0);
                st4(&P[row * 20 + j0 + 4], v1);
                if (t < T - 1) {
                    st4(&g_Pf[t * 256 + row * 16 + j0], v0);
                    st4(&g_Pf[t * 256 + row * 16 + j0 + 4], v1);
                }
            }
            __syncwarp();
            if (lane == 0) flag_rel(t);   // publish K[t] (+ Pf[t])
        }
        return;
    }

    // ------------------------------------------------------------------
    // Role 2: smoother gains (blocks 1..32, warp w -> t = (bid-1)*4 + w)
    // ------------------------------------------------------------------
    if (bid <= 32) {
        for (int idx = tid; idx < 256; idx += 128) {
            int i = idx >> 4, k = idx & 15;
            float av = A[idx];
            float f = (i == k ? 1.0f : 0.0f) + DT * av;
            Fb[i * 20 + k] = f; Ftb[k * 20 + i] = f;
            Qb[i * 20 + k] = Q[idx];
        }
        __syncthreads();

        const int t = (bid - 1) * 4 + wrp;
        if (t >= T - 1) return;

        wait_flag(t);
        float* Pf = Pfw[wrp];
        for (int idx = lane; idx < 256; idx += 32)
            Pf[(idx >> 4) * 20 + (idx & 15)] = g_Pf[t * 256 + idx];
        __syncwarp();

        const int row = lane >> 1, h = lane & 1, j0 = h * 8;
        float frow[16];
        #pragma unroll
        for (int k = 0; k < 16; ++k) frow[k] = Fb[row * 20 + k];

        float a[8], w[8];
        #pragma unroll
        for (int j = 0; j < 8; ++j) w[j] = 0.0f;
        #pragma unroll
        for (int k = 0; k < 16; ++k) {
            float fv = frow[k];
            float4 p0 = ld4(&Pf[k * 20 + j0]);
            float4 p1 = ld4(&Pf[k * 20 + j0 + 4]);
            w[0] = fmaf(fv, p0.x, w[0]); w[1] = fmaf(fv, p0.y, w[1]);
            w[2] = fmaf(fv, p0.z, w[2]); w[3] = fmaf(fv, p0.w, w[3]);
            w[4] = fmaf(fv, p1.x, w[4]); w[5] = fmaf(fv, p1.y, w[5]);
            w[6] = fmaf(fv, p1.z, w[6]); w[7] = fmaf(fv, p1.w, w[7]);
        }
        {
            float wk[16];
            #pragma unroll
            for (int j = 0; j < 8; ++j) {
                wk[j0 + j] = w[j];
                wk[(j0 ^ 8) + j] = shflx(w[j], 1);
            }
            float4 q0 = ld4(&Qb[row * 20 + j0]);
            float4 q1 = ld4(&Qb[row * 20 + j0 + 4]);
            a[0] = q0.x; a[1] = q0.y; a[2] = q0.z; a[3] = q0.w;
            a[4] = q1.x; a[5] = q1.y; a[6] = q1.z; a[7] = q1.w;
            #pragma unroll
            for (int k = 0; k < 16; ++k) {
                float wv = wk[k];
                float4 f0 = ld4(&Ftb[k * 20 + j0]);
                float4 f1 = ld4(&Ftb[k * 20 + j0 + 4]);
                a[0] = fmaf(wv, f0.x, a[0]); a[1] = fmaf(wv, f0.y, a[1]);
                a[2] = fmaf(wv, f0.z, a[2]); a[3] = fmaf(wv, f0.w, a[3]);
                a[4] = fmaf(wv, f1.x, a[4]); a[5] = fmaf(wv, f1.y, a[5]);
                a[6] = fmaf(wv, f1.z, a[6]); a[7] = fmaf(wv, f1.w, a[7]);
            }
        }
        #pragma unroll
        for (int p = 0; p < 16; ++p) {
            const int hp = (p >= 8) ? 1 : 0;
            float cand = a[p & 7];
            float f_num = shfl(cand, (row << 1) | hp);
            float diag  = shfl(cand, (p << 1) | hp);
            const int src = (p << 1) | h;
            float pa[8], pw[8];
            #pragma unroll
            for (int j = 0; j < 8; ++j) { pa[j] = shfl(a[j], src); pw[j] = shfl(w[j], src); }
            float f = (row == p) ? 0.0f : f_num * rcpa(diag);
            #pragma unroll
            for (int j = 0; j < 8; ++j) {
                a[j] = fmaf(-f, pa[j], a[j]);
                w[j] = fmaf(-f, pw[j], w[j]);
            }
        }
        const int ri = row & 7;
        float s01 = (ri & 1) ? a[1] : a[0];
        float s23 = (ri & 1) ? a[3] : a[2];
        float s45 = (ri & 1) ? a[5] : a[4];
        float s67 = (ri & 1) ? a[7] : a[6];
        float t0 = (ri & 2) ? s23 : s01;
        float t1 = (ri & 2) ? s67 : s45;
        float cand_r = (ri & 4) ? t1 : t0;
        float diag_r = shfl(cand_r, (row << 1) | ((row >= 8) ? 1 : 0));
        float invd = rcpa(diag_r);
        st4(&g_Xs[t * 256 + row * 16 + j0],
            make_float4(w[0] * invd, w[1] * invd, w[2] * invd, w[3] * invd));
        st4(&g_Xs[t * 256 + row * 16 + j0 + 4],
            make_float4(w[4] * invd, w[5] * invd, w[6] * invd, w[7] * invd));
        return;
    }

    // ------------------------------------------------------------------
    // Role 3: forward state filter (blocks 33..288; 2 batches/warp)
    // ------------------------------------------------------------------
    {
        const int L = lane;
        const int gw = (bid - 33) * 4 + wrp;
        const int b = gw * 2 + (L >> 4);
        const int i = L & 15;

        float arow[16], hrow[16], brow[4];
        #pragma unroll
        for (int k = 0; k < 16; ++k) arow[k] = A[i * 16 + k];
        #pragma unroll
        for (int k = 0; k < 16; ++k) hrow[k] = H[(i & 7) * 16 + k];
        #pragma unroll
        for (int c = 0; c < 4; ++c) brow[c] = Bc[i * 4 + c];

        float s = state0[b * 16 + i];
        float u_c = (i < 4) ? controls[(size_t)b * T * 4 + i] : 0.0f;
        float y_c = (i < 8) ? obs[(size_t)b * T * 8 + i] : 0.0f;

        wait_flag(0);
        int fnext = (T > 1) ? flag_acq(1) : 1;

        #pragma unroll 1
        for (int t = 0; t < T; ++t) {
            float u_n = 0.0f, y_n = 0.0f;
            if (t + 1 < T) {
                u_n = (i < 4) ? controls[((size_t)b * T + t + 1) * 4 + i] : 0.0f;
                y_n = (i < 8) ? obs[((size_t)b * T + t + 1) * 8 + i] : 0.0f;
            }
            float kq[8];
            #pragma unroll
            for (int q = 0; q < 8; ++q) kq[q] = g_K[t * 128 + q * 16 + i];

            // s_p = s + DT*(A s + Bc u)
            float a0 = 0.0f, a1 = 0.0f;
            #pragma unroll
            for (int k = 0; k < 8; ++k) {
                a0 = fmaf(arow[k], shfl16(s, k), a0);
                a1 = fmaf(arow[k + 8], shfl16(s, k + 8), a1);
            }
            #pragma unroll
            for (int c = 0; c < 4; ++c) a0 = fmaf(brow[c], shfl16(u_c, c), a0);
            float sp = s + DT * (a0 + a1);
            if (t > 0) g_sp[((size_t)b * T + t) * NS + i] = sp;

            // innov = y - H s_p
            float h0 = 0.0f, h1 = 0.0f;
            #pragma unroll
            for (int k = 0; k < 8; ++k) {
                h0 = fmaf(hrow[k], shfl16(sp, k), h0);
                h1 = fmaf(hrow[k + 8], shfl16(sp, k + 8), h1);
            }
            float iv = y_c - (h0 + h1);

            // s = s_p + K innov
            float acc = sp;
            #pragma unroll
            for (int q = 0; q < 8; ++q) acc = fmaf(kq[q], shfl16(iv, q), acc);
            s = acc;
            out[((size_t)b * T + t) * NS + i] = s;
            u_c = u_n; y_c = y_n;

            // confirm flag for t+1; prefetch status of t+2 (off the critical path)
            if (t + 1 < T) {
                if (!fnext) wait_flag(t + 1);
                fnext = (t + 2 < T) ? flag_acq(t + 2) : 1;
            }
        }
    }
}

// ============================================================================
// Backward smoother (R5 body: 2 batches/warp, xc/spn/sf prefetch).
// ============================================================================
__global__ __launch_bounds__(128) void kf_backward(float* __restrict__ out)
{
    const int L = threadIdx.x & 31;
    const int gw = blockIdx.x * 4 + (threadIdx.x >> 5);
    const int b = gw * 2 + (L >> 4);
    const int i = L & 15;

    float ss = out[((size_t)b * T + (T - 1)) * NS + i];
    float xc[16];
    #pragma unroll
    for (int j = 0; j < 16; ++j) xc[j] = g_Xs[(T - 2) * 256 + j * 16 + i];
    float spn_c = g_sp[((size_t)b * T + (T - 1)) * NS + i];
    float sf_c  = out[((size_t)b * T + (T - 2)) * NS + i];

    #pragma unroll 1
    for (int t = T - 2; t >= 0; --t) {
        float xn[16]; float spn_n = 0.0f, sf_n = 0.0f;
        if (t > 0) {
            #pragma unroll
            for (int j = 0; j < 16; ++j) xn[j] = g_Xs[(t - 1) * 256 + j * 16 + i];
            spn_n = g_sp[((size_t)b * T + t) * NS + i];
            sf_n  = out[((size_t)b * T + t - 1) * NS + i];
        }
        float d = ss - spn_c;
        float m0 = 0.0f, m1 = 0.0f;
        #pragma unroll
        for (int j = 0; j < 8; ++j) {
            m0 = fmaf(shfl16(d, j), xc[j], m0);
            m1 = fmaf(shfl16(d, j + 8), xc[j + 8], m1);
        }
        ss = sf_c + m0 + m1;
        out[((size_t)b * T + t) * NS + i] = ss;
        if (t > 0) {
            #pragma unroll
            for (int j = 0; j < 16; ++j) xc[j] = xn[j];
            spn_c = spn_n; sf_c = sf_n;
        }
    }
}

extern "C" void kernel_launch(void* const* d_in, const int* in_sizes, int n_in,
                              void* d_out, int out_size) {
    (void)in_sizes; (void)n_in; (void)out_size;
    const float* state0   = (const float*)d_in[0];
    const float* P0       = (const float*)d_in[1];
    const float* controls = (const float*)d_in[2];
    const float* obs      = (const float*)d_in[3];
    const float* A        = (const float*)d_in[4];
    const float* Bc       = (const float*)d_in[5];
    const float* H        = (const float*)d_in[6];
    const float* Q        = (const float*)d_in[7];
    const float* R        = (const float*)d_in[8];
    float* out = (float*)d_out;

    kf_reset<<<1, 128>>>();
    kf_fused<<<33 + BATCH / 8, 128>>>(state0, P0, controls, obs, A, Bc, H, Q, R, out);
    kf_backward<<<BATCH / 8, 128>>>(out);
}